// round 14
// baseline (speedup 1.0000x reference)
#include <cuda_runtime.h>
#include <cuda_bf16.h>
#include <stdint.h>

// Problem constants
#define PD 64      // splits
#define KD 64      // samples per side
#define ND 128     // points per split
#define DD 2048    // feature dim
#define NCH 4      // D quarters -> 256 CTAs, 2 per SM (all co-resident: 256<=296)
#define KC (DD / NCH)     // 512 K per CTA
#define NCHK (KC / 64)    // 8 chunks of 64 K

// Scratch (device globals; zero-initialized; counters self-reset)
__device__ float g_part[NCH][PD][ND][ND];  // partial grams, 16 MB
__device__ float g_diag[NCH][PD][ND];      // partial gram diagonals (coalesced)
__device__ float g_bw[NCH][PD][2];         // per-quarter (sum(G), trace(G))
__device__ float g_sums[PD][4];            // xx, xy, yx, yy per split
__device__ float g_l2max4[4];              // quadrant maxes for split PD-1
__device__ unsigned int g_flag[PD];        // per-split arrivals (self-reset)
__device__ unsigned int g_done[PD];        // per-split epilogue-done (self-reset)
__device__ unsigned int g_ctr;             // global finalize counter (self-reset)

__device__ __forceinline__ uint32_t smem_u32(const void* p) {
    uint32_t a;
    asm("{ .reg .u64 t; cvta.to.shared.u64 t, %1; cvt.u32.u64 %0, t; }"
        : "=r"(a) : "l"(p));
    return a;
}

// Read-once streaming load (ld.global.cs = evict-first semantics, any width).
__device__ __forceinline__ float4 ldg_stream(const float* p) {
    return __ldcs((const float4*)p);
}

__device__ __forceinline__ void ldsm_x4(uint32_t& r0, uint32_t& r1, uint32_t& r2,
                                        uint32_t& r3, uint32_t addr) {
    asm volatile("ldmatrix.sync.aligned.m8n8.x4.shared.b16 {%0,%1,%2,%3}, [%4];"
                 : "=r"(r0), "=r"(r1), "=r"(r2), "=r"(r3) : "r"(addr));
}

__device__ __forceinline__ void mma_bf16(float* c, const uint32_t* a, const uint32_t* b) {
    asm volatile(
        "mma.sync.aligned.m16n8k16.row.col.f32.bf16.bf16.f32 "
        "{%0,%1,%2,%3}, {%4,%5,%6,%7}, {%8,%9}, {%0,%1,%2,%3};"
        : "+f"(c[0]), "+f"(c[1]), "+f"(c[2]), "+f"(c[3])
        : "r"(a[0]), "r"(a[1]), "r"(a[2]), "r"(a[3]), "r"(b[0]), "r"(b[1]));
}

__device__ __forceinline__ unsigned int ld_acquire(const unsigned int* p) {
    unsigned int v;
    asm volatile("ld.acquire.gpu.u32 %0, [%1];" : "=r"(v) : "l"(p) : "memory");
    return v;
}

// ---------------------------------------------------------------------------
// Fully fused kernel (proven R12 structure). blockIdx.x = quarter, .y = split.
// This round: streaming (.cs) hints on all read-once traffic so the gram
// partials survive in L2 across the phase-1 -> phase-2 handoff.
// ---------------------------------------------------------------------------
__global__ void __launch_bounds__(256, 2) fused_kernel(const float* __restrict__ src,
                                                       const float* __restrict__ tgt,
                                                       float* __restrict__ out) {
    const int nc = blockIdx.x;
    const int p  = blockIdx.y;
    const int t  = threadIdx.x;
    const int lane = t & 31;
    const int w    = t >> 5;

    __shared__ __align__(16) __nv_bfloat16 tile[2][ND][72];
    __shared__ float red1[8], red2[8];
    __shared__ float diag[ND];
    __shared__ unsigned int s_last;

    // ---- loader mapping: thread t loads 8 rows (rb + 16s), one float4 each ----
    const int f4 = t & 15;
    const int rb = t >> 4;
    const float* rowp[8];
#pragma unroll
    for (int s = 0; s < 8; s++) {
        int r = rb + 16 * s;
        const float* base = (r < KD) ? (src + (size_t)(p * KD + r) * DD)
                                     : (tgt + (size_t)(p * KD + (r - KD)) * DD);
        rowp[s] = base + nc * KC + f4 * 4;
    }
    char* tbase[2] = { (char*)&tile[0][0][0], (char*)&tile[1][0][0] };
    uint32_t sts[8];
#pragma unroll
    for (int s = 0; s < 8; s++)
        sts[s] = (uint32_t)((rb + 16 * s) * 144 + f4 * 8);

    // ---- mma mapping: warp tile at (wm, wn) ----
    const int wm = (w & 3) << 5;
    const int wn = (w >> 2) << 6;
    uint32_t tb[2] = { smem_u32(tbase[0]), smem_u32(tbase[1]) };
    uint32_t aaddr[2][2], baddr[2][4];
#pragma unroll
    for (int b = 0; b < 2; b++) {
#pragma unroll
        for (int mi = 0; mi < 2; mi++)
            aaddr[b][mi] = tb[b] + (uint32_t)((wm + mi * 16 + (lane & 15)) * 144
                                              + (lane >> 4) * 16);
#pragma unroll
        for (int nj = 0; nj < 4; nj++)
            baddr[b][nj] = tb[b] + (uint32_t)((wn + nj * 16 + ((lane >> 4) << 3)
                                               + (lane & 7)) * 144
                                              + ((lane >> 3) & 1) * 16);
    }

    float acc[2][8][4];
#pragma unroll
    for (int mi = 0; mi < 2; mi++)
#pragma unroll
        for (int nj = 0; nj < 8; nj++)
#pragma unroll
            for (int r = 0; r < 4; r++) acc[mi][nj][r] = 0.f;

    float4 v[8];
#pragma unroll
    for (int s = 0; s < 8; s++) v[s] = ldg_stream(rowp[s]);
#pragma unroll
    for (int s = 0; s < 8; s++) {
        __nv_bfloat162 lo = __floats2bfloat162_rn(v[s].x, v[s].y);
        __nv_bfloat162 hi = __floats2bfloat162_rn(v[s].z, v[s].w);
        uint2 u = { *(uint32_t*)&lo, *(uint32_t*)&hi };
        *(uint2*)(tbase[0] + sts[s]) = u;
    }
    __syncthreads();

    uint32_t afr[2][2][4], bfr[2][8][2];

    for (int ch = 0; ch < NCHK; ch++) {
        const int b = ch & 1;
        if (ch + 1 < NCHK) {
#pragma unroll
            for (int s = 0; s < 8; s++)
                v[s] = ldg_stream(rowp[s] + (ch + 1) * 64);
        }

        ldsm_x4(afr[0][0][0], afr[0][0][1], afr[0][0][2], afr[0][0][3], aaddr[b][0]);
        ldsm_x4(afr[0][1][0], afr[0][1][1], afr[0][1][2], afr[0][1][3], aaddr[b][1]);
#pragma unroll
        for (int nj = 0; nj < 4; nj++)
            ldsm_x4(bfr[0][2 * nj][0], bfr[0][2 * nj][1],
                    bfr[0][2 * nj + 1][0], bfr[0][2 * nj + 1][1], baddr[b][nj]);

#pragma unroll
        for (int k16 = 0; k16 < 4; k16++) {
            const int cur = k16 & 1;
            const int nxt = cur ^ 1;
            if (k16 < 3) {
                ldsm_x4(afr[nxt][0][0], afr[nxt][0][1], afr[nxt][0][2],
                        afr[nxt][0][3], aaddr[b][0] + (k16 + 1) * 32);
                ldsm_x4(afr[nxt][1][0], afr[nxt][1][1], afr[nxt][1][2],
                        afr[nxt][1][3], aaddr[b][1] + (k16 + 1) * 32);
#pragma unroll
                for (int nj = 0; nj < 4; nj++)
                    ldsm_x4(bfr[nxt][2 * nj][0], bfr[nxt][2 * nj][1],
                            bfr[nxt][2 * nj + 1][0], bfr[nxt][2 * nj + 1][1],
                            baddr[b][nj] + (k16 + 1) * 32);
            }
#pragma unroll
            for (int mi = 0; mi < 2; mi++)
#pragma unroll
                for (int nj = 0; nj < 8; nj++)
                    mma_bf16(acc[mi][nj], afr[cur][mi], bfr[cur][nj]);
        }

        if (ch + 1 < NCHK) {
            char* dst = tbase[(ch + 1) & 1];
#pragma unroll
            for (int s = 0; s < 8; s++) {
                __nv_bfloat162 lo = __floats2bfloat162_rn(v[s].x, v[s].y);
                __nv_bfloat162 hi = __floats2bfloat162_rn(v[s].z, v[s].w);
                uint2 u = { *(uint32_t*)&lo, *(uint32_t*)&hi };
                *(uint2*)(dst + sts[s]) = u;
            }
            __syncthreads();
        }
    }

    // ---- writeout + (sum, trace) + diagonal ----
    float* outp = &g_part[nc][p][0][0];
    float* diagp = &g_diag[nc][p][0];
    const int rr = lane >> 2;
    const int cc = (lane & 3) * 2;
    float s1 = 0.f, s2 = 0.f;
#pragma unroll
    for (int mi = 0; mi < 2; mi++)
#pragma unroll
        for (int nj = 0; nj < 8; nj++) {
            int row = wm + mi * 16 + rr;
            int col = wn + nj * 8 + cc;
            *(float2*)&outp[row * ND + col] =
                make_float2(acc[mi][nj][0], acc[mi][nj][1]);
            *(float2*)&outp[(row + 8) * ND + col] =
                make_float2(acc[mi][nj][2], acc[mi][nj][3]);
            s1 += (acc[mi][nj][0] + acc[mi][nj][1]) +
                  (acc[mi][nj][2] + acc[mi][nj][3]);
            if (row == col)         { s2 += acc[mi][nj][0]; diagp[row]     = acc[mi][nj][0]; }
            if (row == col + 1)     { s2 += acc[mi][nj][1]; diagp[row]     = acc[mi][nj][1]; }
            if (row + 8 == col)     { s2 += acc[mi][nj][2]; diagp[row + 8] = acc[mi][nj][2]; }
            if (row + 8 == col + 1) { s2 += acc[mi][nj][3]; diagp[row + 8] = acc[mi][nj][3]; }
        }
#pragma unroll
    for (int m = 16; m > 0; m >>= 1) {
        s1 += __shfl_xor_sync(0xFFFFFFFFu, s1, m);
        s2 += __shfl_xor_sync(0xFFFFFFFFu, s2, m);
    }
    if (lane == 0) { red1[w] = s1; red2[w] = s2; }
    __syncthreads();
    if (t == 0) {
        float a = 0.f, b2 = 0.f;
#pragma unroll
        for (int k = 0; k < 8; k++) { a += red1[k]; b2 += red2[k]; }
        g_bw[nc][p][0] = a;
        g_bw[nc][p][1] = b2;
        __threadfence();
        atomicAdd(&g_flag[p], 1u);
        while (ld_acquire(&g_flag[p]) < 4u) { }
    }
    __syncthreads();   // all threads: siblings' grams now visible

    // ================= Phase 2: quadrant q = nc of split p =================
    const int q = nc;
    const int i  = ((q >> 1) << 6) + (t >> 2);      // row (64 rows/CTA)
    const int jb = ((q & 1) << 6) + (t & 3) * 16;   // 16-col strip

    if (t < ND) {
        float d = 0.f;
#pragma unroll
        for (int c = 0; c < NCH; c++) d += g_diag[c][p][t];
        diag[t] = d;
    }

    float gs = 0.f, tr = 0.f;
#pragma unroll
    for (int c = 0; c < NCH; c++) { gs += g_bw[c][p][0]; tr += g_bw[c][p][1]; }
    const float sumL2 = 2.f * (float)ND * tr - 2.f * gs;
    const float bwv = sumL2 / (float)(ND * ND - ND) * 0.25f;
    const float inv4 = 1.f / (bwv * 16.f + 1e-9f);

    float g[16];
#pragma unroll
    for (int j4 = 0; j4 < 4; j4++) {
        float4 A = ldg_stream(&g_part[0][p][i][jb + j4 * 4]);
        float4 B = ldg_stream(&g_part[1][p][i][jb + j4 * 4]);
        float4 C = ldg_stream(&g_part[2][p][i][jb + j4 * 4]);
        float4 D = ldg_stream(&g_part[3][p][i][jb + j4 * 4]);
        g[4 * j4 + 0] = (A.x + B.x) + (C.x + D.x);
        g[4 * j4 + 1] = (A.y + B.y) + (C.y + D.y);
        g[4 * j4 + 2] = (A.z + B.z) + (C.z + D.z);
        g[4 * j4 + 3] = (A.w + B.w) + (C.w + D.w);
    }
    __syncthreads();

    const float di = diag[i];
    float qs = 0.f, lmax = 0.f;
#pragma unroll
    for (int jj = 0; jj < 16; jj++) {
        float l2 = di + diag[jb + jj] - 2.f * g[jj];
        lmax = fmaxf(lmax, l2);
        float z = __expf(-l2 * inv4);
        float z2 = z * z;
        float z4 = z2 * z2;
        float z8 = z4 * z4;
        float z16 = z8 * z8;
        qs += z + z2 + z4 + z8 + z16;
    }

#pragma unroll
    for (int m = 16; m > 0; m >>= 1) {
        qs += __shfl_xor_sync(0xFFFFFFFFu, qs, m);
        lmax = fmaxf(lmax, __shfl_xor_sync(0xFFFFFFFFu, lmax, m));
    }
    if (lane == 0) { red1[w] = qs; red2[w] = lmax; }
    __syncthreads();

    if (t == 0) {
        float s = 0.f, m = 0.f;
#pragma unroll
        for (int k = 0; k < 8; k++) { s += red1[k]; m = fmaxf(m, red2[k]); }
        g_sums[p][q] = s;                        // q: 0=xx, 1=xy, 2=yx, 3=yy
        if (p == PD - 1) g_l2max4[q] = m;

        unsigned int d = atomicAdd(&g_done[p], 1u);
        if (d == 3u) { g_flag[p] = 0u; g_done[p] = 0u; }

        __threadfence();
        unsigned int done = atomicAdd(&g_ctr, 1u);
        s_last = (done == (unsigned)(NCH * PD - 1)) ? 1u : 0u;
        if (s_last) g_ctr = 0;   // reset for graph replay
    }
    __syncthreads();

    // ================= Phase 3: warp-parallel finalize =================
    if (s_last != 0 && w == 0) {
        __threadfence();   // acquire: all CTAs released via fence+atomic
        float4 a = *(const float4*)&g_sums[lane][0];
        float4 c = *(const float4*)&g_sums[lane + 32][0];
        float X  = a.x + c.x;   // xx
        float XY = a.y + c.y;
        float YX = a.z + c.z;
        float Y  = a.w + c.w;   // yy
#pragma unroll
        for (int m = 16; m > 0; m >>= 1) {
            X  += __shfl_xor_sync(0xFFFFFFFFu, X,  m);
            XY += __shfl_xor_sync(0xFFFFFFFFu, XY, m);
            YX += __shfl_xor_sync(0xFFFFFFFFu, YX, m);
            Y  += __shfl_xor_sync(0xFFFFFFFFu, Y,  m);
        }
        if (lane == 0) {
            X  *= (1.f / 4096.f);
            XY *= (1.f / 4096.f);
            YX *= (1.f / 4096.f);
            Y  *= (1.f / 4096.f);
            float mx = fmaxf(fmaxf(g_l2max4[0], g_l2max4[1]),
                             fmaxf(g_l2max4[2], g_l2max4[3]));
            out[0] = (X + Y - XY - YX) * (1.f / 64.f);  // total_loss
            out[1] = mx;                                // max(l2[-1])
            out[2] = X * (1.f / 64.f);
            out[3] = Y * (1.f / 64.f);
            out[4] = XY * (1.f / 64.f);
            out[5] = YX * (1.f / 64.f);
        }
    }
}

extern "C" void kernel_launch(void* const* d_in, const int* in_sizes, int n_in,
                              void* d_out, int out_size) {
    const float* src = (const float*)d_in[0];
    const float* tgt = (const float*)d_in[1];

    dim3 g1(NCH, PD);
    fused_kernel<<<g1, 256>>>(src, tgt, (float*)d_out);
}